// round 5
// baseline (speedup 1.0000x reference)
#include <cuda_runtime.h>
#include <cuda_fp16.h>
#include <cstdint>

#define CDIM 256
#define KCB  8192
#define NTOK 16384
#define OUT_ELEMS (16*256*32*32)

#define MTHREADS 512          // vq_main threads (16 warps)
#define ITERS   64            // codebook tiles of 128 codewords
#define CHUNKS  (ITERS*2)     // k split in halves of 128 channels
#define SA_BYTES 65536        // A: 128 tok x 256 ch fp16, rows 512B
#define SB_BYTES 32768        // B chunk: 128 cw x 128 ch fp16, rows 256B
#define NSTAGE  3
#define SMEM_TOTAL (SA_BYTES + NSTAGE*SB_BYTES)
#define MARGIN 4e-4f

__device__ float  g_en[KCB * CDIM];
__device__ float  g_corr[KCB];
__device__ __align__(16) __half g_e[KCB * CDIM];
__device__ float  g_zf[NTOK * CDIM];
__device__ __align__(16) __half g_z[NTOK * CDIM];
__device__ int    g_idx[NTOK];
__device__ float  g_margin[NTOK];

// ---------------- helpers ----------------
__device__ __forceinline__ uint32_t smem_u32(const void* p) {
    uint32_t a;
    asm("{ .reg .u64 t; cvta.to.shared.u64 t, %1; cvt.u32.u64 %0, t; }" : "=r"(a) : "l"(p));
    return a;
}
#define CP16(dst, src) asm volatile("cp.async.cg.shared.global [%0], [%1], 16;" :: "r"(dst), "l"(src) : "memory")
#define CP_COMMIT()    asm volatile("cp.async.commit_group;" ::: "memory")
#define CP_WAIT1()     asm volatile("cp.async.wait_group 1;" ::: "memory")
#define CP_WAIT0()     asm volatile("cp.async.wait_group 0;" ::: "memory")

__device__ __forceinline__ void ldsm4(uint32_t& r0, uint32_t& r1, uint32_t& r2, uint32_t& r3, uint32_t a) {
    asm volatile("ldmatrix.sync.aligned.m8n8.x4.shared.b16 {%0,%1,%2,%3}, [%4];"
                 : "=r"(r0), "=r"(r1), "=r"(r2), "=r"(r3) : "r"(a));
}
__device__ __forceinline__ void mma16816(float* d, const uint32_t* a, const uint32_t* b) {
    asm volatile("mma.sync.aligned.m16n8k16.row.col.f32.f16.f16.f32 "
                 "{%0,%1,%2,%3}, {%4,%5,%6,%7}, {%8,%9}, {%0,%1,%2,%3};"
                 : "+f"(d[0]), "+f"(d[1]), "+f"(d[2]), "+f"(d[3])
                 : "r"(a[0]), "r"(a[1]), "r"(a[2]), "r"(a[3]), "r"(b[0]), "r"(b[1]));
}
__device__ __forceinline__ unsigned fmap(float v) {
    unsigned u = __float_as_uint(v);
    return (u & 0x80000000u) ? ~u : (u | 0x80000000u);
}
__device__ __forceinline__ float funmap(unsigned u) {
    return __uint_as_float((u & 0x80000000u) ? (u ^ 0x80000000u) : ~u);
}

// ---------------- preprocessing ----------------
__global__ void norm_codebook(const float* __restrict__ emb) {
    int row  = blockIdx.x * 8 + (threadIdx.x >> 5);
    int lane = threadIdx.x & 31;
    const float4* w = (const float4*)(emb + (size_t)row * CDIM);
    float4 a = __ldg(w + lane);
    float4 b = __ldg(w + lane + 32);
    float ss = a.x*a.x + a.y*a.y + a.z*a.z + a.w*a.w
             + b.x*b.x + b.y*b.y + b.z*b.z + b.w*b.w;
    #pragma unroll
    for (int s = 16; s; s >>= 1) ss += __shfl_xor_sync(0xffffffffu, ss, s);
    float inv = 1.0f / fmaxf(sqrtf(ss), 1e-12f);
    float v[8];
    v[0]=a.x*inv; v[1]=a.y*inv; v[2]=a.z*inv; v[3]=a.w*inv;
    v[4]=b.x*inv; v[5]=b.y*inv; v[6]=b.z*inv; v[7]=b.w*inv;
    float4* o = (float4*)(g_en + (size_t)row * CDIM);
    o[lane]      = make_float4(v[0], v[1], v[2], v[3]);
    o[lane + 32] = make_float4(v[4], v[5], v[6], v[7]);
    // fp16 copy: pack 4 halfs (two half2) per segment -> full 8B stores
    __half2* he = (__half2*)(g_e + (size_t)row * CDIM);
    he[lane*2]      = __floats2half2_rn(v[0], v[1]);
    he[lane*2 + 1]  = __floats2half2_rn(v[2], v[3]);
    he[64 + lane*2]     = __floats2half2_rn(v[4], v[5]);
    he[64 + lane*2 + 1] = __floats2half2_rn(v[6], v[7]);
    float ss2 = 0.f;
    #pragma unroll
    for (int j = 0; j < 8; j++) ss2 = fmaf(v[j], v[j], ss2);
    #pragma unroll
    for (int s = 16; s; s >>= 1) ss2 += __shfl_xor_sync(0xffffffffu, ss2, s);
    if (lane == 0) g_corr[row] = 0.5f * ss2;
}

// 128 tokens per block (one aligned hw-slice of one batch image), 256 threads.
__global__ void __launch_bounds__(256) norm_tokens(const float* __restrict__ z) {
    __shared__ float ssh[2][128];
    int n0 = blockIdx.x * 128;
    int b   = n0 >> 10;
    int hw0 = n0 & 1023;
    int tt = threadIdx.x & 127;        // token within block
    int p  = threadIdx.x >> 7;         // channel half (0/1)
    const float* zp = z + ((size_t)b * CDIM + p * 128) * 1024 + hw0 + tt;

    float ss = 0.f;
    #pragma unroll 8
    for (int c = 0; c < 128; c++) { float v = zp[(size_t)c * 1024]; ss = fmaf(v, v, ss); }
    ssh[p][tt] = ss;
    __syncthreads();
    float inv = 1.0f / fmaxf(sqrtf(ssh[0][tt] + ssh[1][tt]), 1e-12f);

    int n = n0 + tt;
    float*  zfout = g_zf + (size_t)n * CDIM + p * 128;
    __half* zhout = g_z  + (size_t)n * CDIM + p * 128;
    #pragma unroll 2
    for (int c = 0; c < 128; c += 8) {
        float v[8];
        #pragma unroll
        for (int j = 0; j < 8; j++) v[j] = zp[(size_t)(c + j) * 1024] * inv;
        *(float4*)(zfout + c)     = make_float4(v[0], v[1], v[2], v[3]);
        *(float4*)(zfout + c + 4) = make_float4(v[4], v[5], v[6], v[7]);
        __half2 h[4];
        #pragma unroll
        for (int j = 0; j < 4; j++) h[j] = __floats2half2_rn(v[2*j], v[2*j+1]);
        *(uint4*)(zhout + c) = *(uint4*)h;
    }
}

// ---------------- main: HMMA GEMM + fused top-2 (16 warps, 32x32 warp tile) ----------------
__global__ void __launch_bounds__(MTHREADS, 1) vq_main() {
    extern __shared__ __align__(128) char smem[];
    const uint32_t sa = smem_u32(smem);
    const int tid = threadIdx.x, lane = tid & 31, wid = tid >> 5;
    const int wm = wid >> 2, wn = wid & 3;
    const int n0 = blockIdx.x * 128;

    // ---- prologue: A tile + first 2 B chunks ----
    {
        #pragma unroll
        for (int j = 0; j < 8; j++) {               // A: 4096 16B units
            int i = tid + j * MTHREADS;
            int r = i >> 5, q = i & 31;
            uint32_t dst = sa + r*512 + ((q*16) ^ ((r & 7) << 4));
            CP16(dst, g_z + (size_t)(n0 + r) * CDIM + q*8);
        }
        #pragma unroll
        for (int j = 0; j < 4; j++) {               // B chunk 0
            int i = tid + j * MTHREADS;
            int r = i >> 4, q = i & 15;
            uint32_t dst = sa + SA_BYTES + r*256 + ((q*16) ^ ((r & 7) << 4));
            CP16(dst, g_e + (size_t)r * CDIM + q*8);
        }
        CP_COMMIT();
        #pragma unroll
        for (int j = 0; j < 4; j++) {               // B chunk 1
            int i = tid + j * MTHREADS;
            int r = i >> 4, q = i & 15;
            uint32_t dst = sa + SA_BYTES + SB_BYTES + r*256 + ((q*16) ^ ((r & 7) << 4));
            CP16(dst, g_e + (size_t)r * CDIM + 128 + q*8);
        }
        CP_COMMIT();
    }

    float acc[2][4][4];
    float v1[4], v2[4];
    int   i1[4];
    #pragma unroll
    for (int rr = 0; rr < 4; rr++) { v1[rr] = -1e30f; v2[rr] = -1e30f; i1[rr] = 0; }

    const int arow = wm*32 + (lane & 15);                 // + mt*16
    const int akob = (lane >> 4) << 4;
    const int nl   = (lane & 7) | ((lane & 16) >> 1);     // + wn*32 + fj*16
    const int bkob = (lane & 8) << 1;
    const int codebase0 = wn*32 + (lane & 3)*2;

    for (int c = 0; c < CHUNKS; c++) {
        int iter = c >> 1, half = c & 1, st = c % 3;
        if (c == CHUNKS - 1) CP_WAIT0(); else CP_WAIT1();
        __syncthreads();

        if (half == 0) {
            #pragma unroll
            for (int mt = 0; mt < 2; mt++)
                #pragma unroll
                for (int f = 0; f < 4; f++)
                    #pragma unroll
                    for (int e = 0; e < 4; e++) acc[mt][f][e] = 0.f;
        }

        const uint32_t sb = sa + SA_BYTES + st * SB_BYTES;
        #pragma unroll
        for (int kk = 0; kk < 8; kk++) {
            uint32_t a[2][4], b[4][2];
            int kAb = (half*128 + kk*16)*2 + akob;
            #pragma unroll
            for (int mt = 0; mt < 2; mt++) {
                int row = arow + mt*16;
                ldsm4(a[mt][0], a[mt][1], a[mt][2], a[mt][3],
                      sa + row*512 + (kAb ^ ((row & 7) << 4)));
            }
            int kBb = kk*32 + bkob;
            #pragma unroll
            for (int fj = 0; fj < 2; fj++) {
                int n = wn*32 + fj*16 + nl;
                ldsm4(b[2*fj][0], b[2*fj][1], b[2*fj+1][0], b[2*fj+1][1],
                      sb + n*256 + (kBb ^ ((n & 7) << 4)));
            }
            #pragma unroll
            for (int mt = 0; mt < 2; mt++)
                #pragma unroll
                for (int f = 0; f < 4; f++)
                    mma16816(acc[mt][f], a[mt], b[f]);
        }
        __syncthreads();

        if (c + 2 < CHUNKS) {
            int ni = (c + 2) >> 1, nh = (c + 2) & 1, ns = (c + 2) % 3;
            uint32_t db = sa + SA_BYTES + ns * SB_BYTES;
            const __half* src0 = g_e + (size_t)ni * 128 * CDIM + nh * 128;
            #pragma unroll
            for (int j = 0; j < 4; j++) {
                int i = tid + j * MTHREADS;
                int r = i >> 4, q = i & 15;
                CP16(db + r*256 + ((q*16) ^ ((r & 7) << 4)),
                     src0 + (size_t)r * CDIM + q*8);
            }
        }
        CP_COMMIT();

        if (half == 1) {
            int codebase = iter*128 + codebase0;
            #pragma unroll
            for (int mt = 0; mt < 2; mt++)
                #pragma unroll
                for (int f = 0; f < 4; f++)
                    #pragma unroll
                    for (int e = 0; e < 4; e++) {
                        float s = acc[mt][f][e];
                        int rr = mt*2 + (e >> 1);
                        int code = codebase + f*8 + (e & 1);
                        if (s > v1[rr]) { v2[rr] = v1[rr]; v1[rr] = s; i1[rr] = code; }
                        else if (s > v2[rr]) v2[rr] = s;
                    }
        }
    }

    // ---- reduction: 4 lanes/row within warp, then 4 wn-warps via smem ----
    __syncthreads();
    unsigned long long* SK = (unsigned long long*)smem;          // [4][128]
    float* SV2 = (float*)(smem + 4*128*8);                       // [4][128]

    #pragma unroll
    for (int rr = 0; rr < 4; rr++) {
        unsigned long long k = ((unsigned long long)fmap(v1[rr]) << 32)
                             | (unsigned)(KCB - 1 - i1[rr]);
        float a1 = v1[rr], a2 = v2[rr];
        #pragma unroll
        for (int x = 1; x <= 2; x <<= 1) {
            unsigned long long ok = __shfl_xor_sync(0xffffffffu, k, x);
            float b1 = __shfl_xor_sync(0xffffffffu, a1, x);
            float b2 = __shfl_xor_sync(0xffffffffu, a2, x);
            a2 = fmaxf(fmaxf(a2, b2), fminf(a1, b1));
            if (ok > k) { k = ok; a1 = b1; }
        }
        if ((lane & 3) == 0) {
            int m = wm*32 + (rr >> 1)*16 + (rr & 1)*8 + (lane >> 2);
            SK[wn*128 + m] = k;
            SV2[wn*128 + m] = a2;
        }
    }
    __syncthreads();
    if (tid < 128) {
        unsigned long long kw = SK[tid];
        float v1f = funmap((unsigned)(kw >> 32));
        float v2f = SV2[tid];
        #pragma unroll
        for (int w = 1; w < 4; w++) {
            unsigned long long ko = SK[w*128 + tid];
            float vo1 = funmap((unsigned)(ko >> 32));
            float vo2 = SV2[w*128 + tid];
            v2f = fmaxf(fmaxf(v2f, vo2), fminf(v1f, vo1));
            if (ko > kw) { kw = ko; v1f = vo1; }
        }
        g_idx[n0 + tid] = (KCB - 1) - (int)(kw & 0xFFFFFFFFull);
        g_margin[n0 + tid] = v1f - v2f;
    }
}

// ---------------- exact fp32 re-rank for small-margin tokens ----------------
__global__ void __launch_bounds__(128) rerank() {
    int n = blockIdx.x;
    if (g_margin[n] >= MARGIN) return;
    __shared__ float tz[CDIM];
    __shared__ unsigned long long red[4];
    for (int c = threadIdx.x; c < CDIM; c += 128) tz[c] = g_zf[(size_t)n * CDIM + c];
    __syncthreads();
    unsigned long long best = 0ull;
    for (int k = threadIdx.x; k < KCB; k += 128) {
        const float4* e = (const float4*)(g_en + (size_t)k * CDIM);
        float s = 0.f;
        #pragma unroll 8
        for (int c4 = 0; c4 < CDIM/4; c4++) {
            float4 ev = __ldg(e + c4);
            s = fmaf(ev.x, tz[c4*4+0], s);
            s = fmaf(ev.y, tz[c4*4+1], s);
            s = fmaf(ev.z, tz[c4*4+2], s);
            s = fmaf(ev.w, tz[c4*4+3], s);
        }
        s -= g_corr[k];
        unsigned long long p = ((unsigned long long)fmap(s) << 32)
                             | (unsigned)(KCB - 1 - k);
        if (p > best) best = p;
    }
    #pragma unroll
    for (int sft = 16; sft; sft >>= 1) {
        unsigned long long o = __shfl_xor_sync(0xffffffffu, best, sft);
        if (o > best) best = o;
    }
    int lane = threadIdx.x & 31, warp = threadIdx.x >> 5;
    if (lane == 0) red[warp] = best;
    __syncthreads();
    if (threadIdx.x == 0) {
        unsigned long long p = red[0];
        #pragma unroll
        for (int w = 1; w < 4; w++) if (red[w] > p) p = red[w];
        g_idx[n] = (KCB - 1) - (int)(p & 0xFFFFFFFFull);
    }
}

// ---------------- output ----------------
__global__ void __launch_bounds__(256) gather_out(float* __restrict__ out) {
    __shared__ float s[32][CDIM + 1];
    __shared__ int sidx[32];
    int n0 = blockIdx.x * 32;
    if (threadIdx.x < 32) sidx[threadIdx.x] = g_idx[n0 + threadIdx.x];
    __syncthreads();
    #pragma unroll 4
    for (int i = 0; i < 32; i++) {
        int lin = threadIdx.x + i * 256;
        int t = lin >> 8, c = lin & 255;
        s[t][c] = g_en[(size_t)sidx[t] * CDIM + c];
    }
    __syncthreads();
    int b   = n0 >> 10;
    int hw0 = n0 & 1023;
    #pragma unroll 4
    for (int i = 0; i < 32; i++) {
        int lin = threadIdx.x + i * 256;
        int c = lin >> 5, t = lin & 31;
        out[((size_t)b * CDIM + c) * 1024 + hw0 + t] = s[t][c];
    }
}

__global__ void idx_out(float* __restrict__ o) {
    int n = blockIdx.x * 256 + threadIdx.x;
    o[n] = (float)g_idx[n];
}

extern "C" void kernel_launch(void* const* d_in, const int* in_sizes, int n_in,
                              void* d_out, int out_size) {
    const float* z   = (const float*)d_in[0];
    const float* emb = (const float*)d_in[1];
    float* out = (float*)d_out;

    cudaFuncSetAttribute(vq_main, cudaFuncAttributeMaxDynamicSharedMemorySize, SMEM_TOTAL);

    norm_codebook<<<KCB / 8, 256>>>(emb);
    norm_tokens<<<NTOK / 128, 256>>>(z);
    vq_main<<<NTOK / 128, MTHREADS, SMEM_TOTAL>>>();
    rerank<<<NTOK, 128>>>();
    gather_out<<<NTOK / 32, 256>>>(out);
    if (out_size >= OUT_ELEMS + NTOK)
        idx_out<<<NTOK / 256, 256>>>(out + OUT_ELEMS);
}